// round 6
// baseline (speedup 1.0000x reference)
#include <cuda_runtime.h>
#include <cstdint>
#include <cstddef>

static constexpr int SEQ = 8192;
static constexpr int DM  = 2048;

// ---------------- static device scratch (allocation-free) ----------------
__device__ __align__(256) float g_Xr[(size_t)SEQ * DM];
__device__ __align__(256) float g_Wq[(size_t)DM * DM];
__device__ __align__(256) float g_Wk[(size_t)DM * DM];
__device__ __align__(256) float g_Wv[(size_t)DM * DM];
__device__ __align__(256) float g_Q [(size_t)SEQ * DM];
__device__ __align__(256) float g_K [(size_t)SEQ * DM];
__device__ __align__(256) float g_VT[(size_t)DM * SEQ];
__device__ __align__(256) float g_S [(size_t)SEQ * SEQ];

// ---------------- helpers ----------------
__device__ __forceinline__ uint32_t smem_u32(const void* p) {
    uint32_t a;
    asm("{ .reg .u64 t; cvta.to.shared.u64 t, %1; cvt.u32.u64 %0, t; }" : "=r"(a) : "l"(p));
    return a;
}
// cvt.rna.tf32.f32 needs a .b32 destination register
__device__ __forceinline__ float rna_tf32(float x) {
    uint32_t r;
    asm("cvt.rna.tf32.f32 %0, %1;" : "=r"(r) : "f"(x));
    return __uint_as_float(r);
}

#define CP_ASYNC16(d, s)  asm volatile("cp.async.cg.shared.global [%0], [%1], 16;" :: "r"((uint32_t)(d)), "l"(s) : "memory")
#define CP_COMMIT()       asm volatile("cp.async.commit_group;" ::: "memory")
#define CP_WAIT1()        asm volatile("cp.async.wait_group 1;" ::: "memory")

// m16n8k8 tf32 mma (sm_80+, valid on plain sm_100 target)
__device__ __forceinline__ void mma8(float c[4], const uint32_t a[4], const uint32_t b[2]) {
    asm volatile(
        "mma.sync.aligned.m16n8k8.row.col.f32.tf32.tf32.f32 "
        "{%0,%1,%2,%3}, {%4,%5,%6,%7}, {%8,%9}, {%0,%1,%2,%3};\n"
        : "+f"(c[0]), "+f"(c[1]), "+f"(c[2]), "+f"(c[3])
        : "r"(a[0]), "r"(a[1]), "r"(a[2]), "r"(a[3]), "r"(b[0]), "r"(b[1]));
}

// ---------------- generic tf32 GEMM: C[m,n] = alpha * sum_k A[m,k]*B[n,k] ----------------
// A:[M,K] row-major, B:[N,K] row-major (i.e. C = A @ B^T), all K%32==0, tiles exact.
static constexpr int BM = 128, BN = 128, BK = 32;
static constexpr int PAD = 36;                 // floats per smem row (conflict-free)
static constexpr int TILE_F  = 128 * PAD;      // floats per A or B tile
static constexpr int STAGE_F = 2 * TILE_F;
static constexpr int NSTG = 3;
static constexpr size_t GEMM_SMEM = (size_t)NSTG * STAGE_F * 4;   // 110592 B

__device__ __forceinline__ void load_stage(float* st, const float* gA, const float* gB, int K) {
    const int tid = threadIdx.x;
    float* sA = st;
    float* sB = st + TILE_F;
#pragma unroll
    for (int i = 0; i < 4; i++) {           // A: 1024 16B-chunks / 256 threads
        int c = tid + 256 * i;
        int row = c >> 3, col16 = c & 7;
        CP_ASYNC16(smem_u32(sA + row * PAD + col16 * 4), gA + (size_t)row * K + col16 * 4);
    }
#pragma unroll
    for (int i = 0; i < 4; i++) {           // B: same shape
        int c = tid + 256 * i;
        int row = c >> 3, col16 = c & 7;
        CP_ASYNC16(smem_u32(sB + row * PAD + col16 * 4), gB + (size_t)row * K + col16 * 4);
    }
}

__global__ void __launch_bounds__(256, 1)
gemm_tf32(float* __restrict__ C, const float* __restrict__ A, const float* __restrict__ B,
          int N, int K, float alpha, int round_out) {
    extern __shared__ float smem[];
    const int tid  = threadIdx.x;
    const int wid  = tid >> 5;
    const int lane = tid & 31;
    const int wm = wid & 3;          // warp row: 4 warps along M (32 rows each)
    const int wn = wid >> 2;         // warp col: 2 warps along N (64 cols each)
    const int g = lane >> 2;         // group id 0..7
    const int t = lane & 3;          // thread-in-group 0..3

    const int tile_m = blockIdx.y * BM;
    const int tile_n = blockIdx.x * BN;

    const float* gA = A + (size_t)tile_m * K;
    const float* gB = B + (size_t)tile_n * K;

    float acc[2][8][4];
#pragma unroll
    for (int i = 0; i < 2; i++)
#pragma unroll
        for (int j = 0; j < 8; j++)
#pragma unroll
            for (int q = 0; q < 4; q++) acc[i][j][q] = 0.f;

    const int nst = K / BK;

    // prologue: stages 0 and 1 in flight
    load_stage(smem,           gA,      gB,      K);  CP_COMMIT();
    load_stage(smem + STAGE_F, gA + BK, gB + BK, K);  CP_COMMIT();

    for (int s = 0; s < nst; s++) {
        CP_WAIT1();              // stage s resident
        __syncthreads();         // all warps done with buffer (s+2)%3's previous contents

        if (s + 2 < nst)
            load_stage(smem + (size_t)((s + 2) % NSTG) * STAGE_F,
                       gA + (size_t)(s + 2) * BK, gB + (size_t)(s + 2) * BK, K);
        CP_COMMIT();             // uniform group accounting

        const float* sA = smem + (size_t)(s % NSTG) * STAGE_F;
        const float* sB = sA + TILE_F;

#pragma unroll
        for (int ks = 0; ks < 4; ks++) {
            const int c0 = ks * 8 + t;
            uint32_t af[2][4];
#pragma unroll
            for (int im = 0; im < 2; im++) {
                const int r = wm * 32 + im * 16 + g;
                af[im][0] = __float_as_uint(sA[r * PAD + c0]);
                af[im][1] = __float_as_uint(sA[(r + 8) * PAD + c0]);
                af[im][2] = __float_as_uint(sA[r * PAD + c0 + 4]);
                af[im][3] = __float_as_uint(sA[(r + 8) * PAD + c0 + 4]);
            }
#pragma unroll
            for (int in = 0; in < 8; in++) {
                const int n = wn * 64 + in * 8 + g;
                uint32_t bf[2];
                bf[0] = __float_as_uint(sB[n * PAD + c0]);
                bf[1] = __float_as_uint(sB[n * PAD + c0 + 4]);
                mma8(acc[0][in], af[0], bf);
                mma8(acc[1][in], af[1], bf);
            }
        }
    }

    // epilogue
#pragma unroll
    for (int im = 0; im < 2; im++) {
        const int row = tile_m + wm * 32 + im * 16 + g;
#pragma unroll
        for (int in = 0; in < 8; in++) {
            const int col = tile_n + wn * 64 + in * 8 + t * 2;
            float2 v0, v1;
            v0.x = acc[im][in][0] * alpha; v0.y = acc[im][in][1] * alpha;
            v1.x = acc[im][in][2] * alpha; v1.y = acc[im][in][3] * alpha;
            if (round_out) {
                v0.x = rna_tf32(v0.x); v0.y = rna_tf32(v0.y);
                v1.x = rna_tf32(v1.x); v1.y = rna_tf32(v1.y);
            }
            *(float2*)(C + (size_t)row * N + col)       = v0;
            *(float2*)(C + (size_t)(row + 8) * N + col) = v1;
        }
    }
}

// ---------------- row softmax, in place on g_S, output rna-rounded ----------------
__global__ void __launch_bounds__(256, 1) softmax_rows(float* __restrict__ S) {
    float4* row = (float4*)(S + (size_t)blockIdx.x * SEQ);
    __shared__ float red[16];
    const int t = threadIdx.x, w = t >> 5;
    float4 v[8];
    float m = -1e30f;
#pragma unroll
    for (int i = 0; i < 8; i++) {
        v[i] = row[t + 256 * i];
        m = fmaxf(m, fmaxf(fmaxf(v[i].x, v[i].y), fmaxf(v[i].z, v[i].w)));
    }
#pragma unroll
    for (int o = 16; o; o >>= 1) m = fmaxf(m, __shfl_xor_sync(~0u, m, o));
    if ((t & 31) == 0) red[w] = m;
    __syncthreads();
    m = red[0];
#pragma unroll
    for (int i = 1; i < 8; i++) m = fmaxf(m, red[i]);

    float s = 0.f;
#pragma unroll
    for (int i = 0; i < 8; i++) {
        v[i].x = __expf(v[i].x - m); v[i].y = __expf(v[i].y - m);
        v[i].z = __expf(v[i].z - m); v[i].w = __expf(v[i].w - m);
        s += (v[i].x + v[i].y) + (v[i].z + v[i].w);
    }
#pragma unroll
    for (int o = 16; o; o >>= 1) s += __shfl_xor_sync(~0u, s, o);
    if ((t & 31) == 0) red[8 + w] = s;
    __syncthreads();
    s = red[8];
#pragma unroll
    for (int i = 9; i < 16; i++) s += red[i];
    const float inv = 1.0f / s;
#pragma unroll
    for (int i = 0; i < 8; i++) {
        float4 o;
        o.x = rna_tf32(v[i].x * inv); o.y = rna_tf32(v[i].y * inv);
        o.z = rna_tf32(v[i].z * inv); o.w = rna_tf32(v[i].w * inv);
        row[t + 256 * i] = o;
    }
}

// ---------------- tf32 rna pre-rounding ----------------
__global__ void round_tf32(float* __restrict__ dst, const float* __restrict__ src, int n4) {
    int i = blockIdx.x * blockDim.x + threadIdx.x;
    if (i < n4) {
        float4 a = ((const float4*)src)[i];
        a.x = rna_tf32(a.x); a.y = rna_tf32(a.y);
        a.z = rna_tf32(a.z); a.w = rna_tf32(a.w);
        ((float4*)dst)[i] = a;
    }
}

// ---------------- launch ----------------
extern "C" void kernel_launch(void* const* d_in, const int* in_sizes, int n_in,
                              void* d_out, int out_size) {
    const float* x  = (const float*)d_in[0];
    const float* wq = (const float*)d_in[1];
    const float* wk = (const float*)d_in[2];
    const float* wv = (const float*)d_in[3];
    float* out = (float*)d_out;

    cudaFuncSetAttribute(gemm_tf32, cudaFuncAttributeMaxDynamicSharedMemorySize, (int)GEMM_SMEM);

    float *Xr, *Wq, *Wk, *Wv, *Q, *K, *VT, *S;
    cudaGetSymbolAddress((void**)&Xr, g_Xr);
    cudaGetSymbolAddress((void**)&Wq, g_Wq);
    cudaGetSymbolAddress((void**)&Wk, g_Wk);
    cudaGetSymbolAddress((void**)&Wv, g_Wv);
    cudaGetSymbolAddress((void**)&Q,  g_Q);
    cudaGetSymbolAddress((void**)&K,  g_K);
    cudaGetSymbolAddress((void**)&VT, g_VT);
    cudaGetSymbolAddress((void**)&S,  g_S);

    const int nX4 = SEQ * DM / 4, nW4 = DM * DM / 4;
    round_tf32<<<nX4 / 256, 256>>>(Xr, x,  nX4);
    round_tf32<<<nW4 / 256, 256>>>(Wq, wq, nW4);
    round_tf32<<<nW4 / 256, 256>>>(Wk, wk, nW4);
    round_tf32<<<nW4 / 256, 256>>>(Wv, wv, nW4);

    // Q = Xr @ Wq^T   [8192, 2048]  (rna-rounded for the S GEMM)
    gemm_tf32<<<dim3(DM / BN, SEQ / BM), 256, GEMM_SMEM>>>(Q, Xr, Wq, DM, DM, 1.0f, 1);
    // K = Xr @ Wk^T   [8192, 2048]
    gemm_tf32<<<dim3(DM / BN, SEQ / BM), 256, GEMM_SMEM>>>(K, Xr, Wk, DM, DM, 1.0f, 1);
    // VT = Wv @ Xr^T  [2048, 8192]  (V computed pre-transposed, rounded for the O GEMM)
    gemm_tf32<<<dim3(SEQ / BN, DM / BM), 256, GEMM_SMEM>>>(VT, Wv, Xr, SEQ, DM, 1.0f, 1);
    // S = (Q @ K^T) / sqrt(DM)   [8192, 8192]
    gemm_tf32<<<dim3(SEQ / BN, SEQ / BM), 256, GEMM_SMEM>>>(S, Q, K, SEQ, DM,
                                                            0.022097086912079608f, 0);
    // P = softmax(S) in place, rna-rounded
    softmax_rows<<<SEQ, 256>>>(S);
    // out = P @ VT^T   [8192, 2048]
    gemm_tf32<<<dim3(DM / BN, SEQ / BM), 256, GEMM_SMEM>>>(out, S, VT, DM, SEQ, 1.0f, 0);
}

// round 7
// speedup vs baseline: 1.0223x; 1.0223x over previous
#include <cuda_runtime.h>
#include <cstdint>
#include <cstddef>

static constexpr int SEQ = 8192;
static constexpr int DM  = 2048;

// ---------------- static device scratch (allocation-free) ----------------
__device__ __align__(256) float g_Xr[(size_t)SEQ * DM];
__device__ __align__(256) float g_Wq[(size_t)DM * DM];
__device__ __align__(256) float g_Wk[(size_t)DM * DM];
__device__ __align__(256) float g_Wv[(size_t)DM * DM];
__device__ __align__(256) float g_Q [(size_t)SEQ * DM];
__device__ __align__(256) float g_K [(size_t)SEQ * DM];
__device__ __align__(256) float g_VT[(size_t)DM * SEQ];
__device__ __align__(256) float g_S [(size_t)SEQ * SEQ];

// ---------------- helpers ----------------
__device__ __forceinline__ uint32_t smem_u32(const void* p) {
    uint32_t a;
    asm("{ .reg .u64 t; cvta.to.shared.u64 t, %1; cvt.u32.u64 %0, t; }" : "=r"(a) : "l"(p));
    return a;
}
// cvt.rna.tf32.f32 needs a .b32 destination register
__device__ __forceinline__ float rna_tf32(float x) {
    uint32_t r;
    asm("cvt.rna.tf32.f32 %0, %1;" : "=r"(r) : "f"(x));
    return __uint_as_float(r);
}

#define CP_ASYNC16(d, s)  asm volatile("cp.async.cg.shared.global [%0], [%1], 16;" :: "r"((uint32_t)(d)), "l"(s) : "memory")
#define CP_COMMIT()       asm volatile("cp.async.commit_group;" ::: "memory")
#define CP_WAIT1()        asm volatile("cp.async.wait_group 1;" ::: "memory")

// m16n8k8 tf32 mma (sm_80+, valid on plain sm_100 target)
__device__ __forceinline__ void mma8(float c[4], const uint32_t a[4], const uint32_t b[2]) {
    asm volatile(
        "mma.sync.aligned.m16n8k8.row.col.f32.tf32.tf32.f32 "
        "{%0,%1,%2,%3}, {%4,%5,%6,%7}, {%8,%9}, {%0,%1,%2,%3};\n"
        : "+f"(c[0]), "+f"(c[1]), "+f"(c[2]), "+f"(c[3])
        : "r"(a[0]), "r"(a[1]), "r"(a[2]), "r"(a[3]), "r"(b[0]), "r"(b[1]));
}

// ---------------- generic tf32 GEMM: C[m,n] = alpha * sum_k A[m,k]*B[n,k] ----------------
// A:[M,K] row-major, B:[N,K] row-major (C = A @ B^T). M%256==0, N%128==0, K%32==0.
static constexpr int BM = 256, BN = 128, BK = 32;
static constexpr int PAD = 36;                    // floats per smem row (conflict-free, 144B)
static constexpr int A_TILE_F = BM * PAD;         // 9216 floats
static constexpr int B_TILE_F = BN * PAD;         // 4608 floats
static constexpr int STAGE_F  = A_TILE_F + B_TILE_F;
static constexpr int NSTG = 3;
static constexpr size_t GEMM_SMEM = (size_t)NSTG * STAGE_F * 4;   // 165,888 B

__device__ __forceinline__ void load_stage(float* st, const float* gA, const float* gB, int K) {
    const int tid = threadIdx.x;
    float* sA = st;
    float* sB = st + A_TILE_F;
#pragma unroll
    for (int i = 0; i < 8; i++) {           // A: 256 rows * 8 chunks = 2048 / 256 threads
        int c = tid + 256 * i;
        int row = c >> 3, col16 = c & 7;
        CP_ASYNC16(smem_u32(sA + row * PAD + col16 * 4), gA + (size_t)row * K + col16 * 4);
    }
#pragma unroll
    for (int i = 0; i < 4; i++) {           // B: 128 rows * 8 chunks = 1024
        int c = tid + 256 * i;
        int row = c >> 3, col16 = c & 7;
        CP_ASYNC16(smem_u32(sB + row * PAD + col16 * 4), gB + (size_t)row * K + col16 * 4);
    }
}

__global__ void __launch_bounds__(256, 1)
gemm_tf32(float* __restrict__ C, const float* __restrict__ A, const float* __restrict__ B,
          int N, int K, float alpha, int round_out) {
    extern __shared__ float smem[];
    const int tid  = threadIdx.x;
    const int wid  = tid >> 5;
    const int lane = tid & 31;
    const int wm = wid & 3;          // 4 warps along M (64 rows each)
    const int wn = wid >> 2;         // 2 warps along N (64 cols each)
    const int g = lane >> 2;         // 0..7
    const int t = lane & 3;          // 0..3

    // tile-order swizzle: chunks of 8 n-tiles, m-major inside a chunk -> compact waves
    const int id = blockIdx.y * gridDim.x + blockIdx.x;
    const int chunk = id / (8 * gridDim.y);
    const int rem   = id % (8 * gridDim.y);
    const int tile_m = (rem / 8) * BM;
    const int tile_n = (chunk * 8 + (rem & 7)) * BN;

    const float* gA = A + (size_t)tile_m * K;
    const float* gB = B + (size_t)tile_n * K;

    float acc[4][8][4];
#pragma unroll
    for (int i = 0; i < 4; i++)
#pragma unroll
        for (int j = 0; j < 8; j++)
#pragma unroll
            for (int q = 0; q < 4; q++) acc[i][j][q] = 0.f;

    const int nst = K / BK;

    load_stage(smem,           gA,      gB,      K);  CP_COMMIT();
    load_stage(smem + STAGE_F, gA + BK, gB + BK, K);  CP_COMMIT();

    for (int s = 0; s < nst; s++) {
        CP_WAIT1();              // stage s resident
        __syncthreads();

        if (s + 2 < nst)
            load_stage(smem + (size_t)((s + 2) % NSTG) * STAGE_F,
                       gA + (size_t)(s + 2) * BK, gB + (size_t)(s + 2) * BK, K);
        CP_COMMIT();

        const float* sA = smem + (size_t)(s % NSTG) * STAGE_F;
        const float* sB = sA + A_TILE_F;

#pragma unroll
        for (int ks = 0; ks < 4; ks++) {
            const int c0 = ks * 8 + t;
            uint32_t af[4][4];
#pragma unroll
            for (int im = 0; im < 4; im++) {
                const int r = wm * 64 + im * 16 + g;
                af[im][0] = __float_as_uint(sA[r * PAD + c0]);
                af[im][1] = __float_as_uint(sA[(r + 8) * PAD + c0]);
                af[im][2] = __float_as_uint(sA[r * PAD + c0 + 4]);
                af[im][3] = __float_as_uint(sA[(r + 8) * PAD + c0 + 4]);
            }
#pragma unroll
            for (int in = 0; in < 8; in++) {
                const int n = wn * 64 + in * 8 + g;
                uint32_t bf[2];
                bf[0] = __float_as_uint(sB[n * PAD + c0]);
                bf[1] = __float_as_uint(sB[n * PAD + c0 + 4]);
#pragma unroll
                for (int im = 0; im < 4; im++) mma8(acc[im][in], af[im], bf);
            }
        }
    }

    // epilogue
#pragma unroll
    for (int im = 0; im < 4; im++) {
        const int row = tile_m + wm * 64 + im * 16 + g;
#pragma unroll
        for (int in = 0; in < 8; in++) {
            const int col = tile_n + wn * 64 + in * 8 + t * 2;
            float2 v0, v1;
            v0.x = acc[im][in][0] * alpha; v0.y = acc[im][in][1] * alpha;
            v1.x = acc[im][in][2] * alpha; v1.y = acc[im][in][3] * alpha;
            if (round_out) {
                v0.x = rna_tf32(v0.x); v0.y = rna_tf32(v0.y);
                v1.x = rna_tf32(v1.x); v1.y = rna_tf32(v1.y);
            }
            *(float2*)(C + (size_t)row * N + col)       = v0;
            *(float2*)(C + (size_t)(row + 8) * N + col) = v1;
        }
    }
}

// ---------------- row softmax, in place on g_S, output rna-rounded ----------------
__global__ void __launch_bounds__(256, 1) softmax_rows(float* __restrict__ S) {
    float4* row = (float4*)(S + (size_t)blockIdx.x * SEQ);
    __shared__ float red[16];
    const int t = threadIdx.x, w = t >> 5;
    float4 v[8];
    float m = -1e30f;
#pragma unroll
    for (int i = 0; i < 8; i++) {
        v[i] = row[t + 256 * i];
        m = fmaxf(m, fmaxf(fmaxf(v[i].x, v[i].y), fmaxf(v[i].z, v[i].w)));
    }
#pragma unroll
    for (int o = 16; o; o >>= 1) m = fmaxf(m, __shfl_xor_sync(~0u, m, o));
    if ((t & 31) == 0) red[w] = m;
    __syncthreads();
    m = red[0];
#pragma unroll
    for (int i = 1; i < 8; i++) m = fmaxf(m, red[i]);

    float s = 0.f;
#pragma unroll
    for (int i = 0; i < 8; i++) {
        v[i].x = __expf(v[i].x - m); v[i].y = __expf(v[i].y - m);
        v[i].z = __expf(v[i].z - m); v[i].w = __expf(v[i].w - m);
        s += (v[i].x + v[i].y) + (v[i].z + v[i].w);
    }
#pragma unroll
    for (int o = 16; o; o >>= 1) s += __shfl_xor_sync(~0u, s, o);
    if ((t & 31) == 0) red[8 + w] = s;
    __syncthreads();
    s = red[8];
#pragma unroll
    for (int i = 9; i < 16; i++) s += red[i];
    const float inv = 1.0f / s;
#pragma unroll
    for (int i = 0; i < 8; i++) {
        float4 o;
        o.x = rna_tf32(v[i].x * inv); o.y = rna_tf32(v[i].y * inv);
        o.z = rna_tf32(v[i].z * inv); o.w = rna_tf32(v[i].w * inv);
        row[t + 256 * i] = o;
    }
}

// ---------------- tf32 rna pre-rounding ----------------
__global__ void round_tf32(float* __restrict__ dst, const float* __restrict__ src, int n4) {
    int i = blockIdx.x * blockDim.x + threadIdx.x;
    if (i < n4) {
        float4 a = ((const float4*)src)[i];
        a.x = rna_tf32(a.x); a.y = rna_tf32(a.y);
        a.z = rna_tf32(a.z); a.w = rna_tf32(a.w);
        ((float4*)dst)[i] = a;
    }
}

// ---------------- launch ----------------
extern "C" void kernel_launch(void* const* d_in, const int* in_sizes, int n_in,
                              void* d_out, int out_size) {
    const float* x  = (const float*)d_in[0];
    const float* wq = (const float*)d_in[1];
    const float* wk = (const float*)d_in[2];
    const float* wv = (const float*)d_in[3];
    float* out = (float*)d_out;

    cudaFuncSetAttribute(gemm_tf32, cudaFuncAttributeMaxDynamicSharedMemorySize, (int)GEMM_SMEM);

    float *Xr, *Wq, *Wk, *Wv, *Q, *K, *VT, *S;
    cudaGetSymbolAddress((void**)&Xr, g_Xr);
    cudaGetSymbolAddress((void**)&Wq, g_Wq);
    cudaGetSymbolAddress((void**)&Wk, g_Wk);
    cudaGetSymbolAddress((void**)&Wv, g_Wv);
    cudaGetSymbolAddress((void**)&Q,  g_Q);
    cudaGetSymbolAddress((void**)&K,  g_K);
    cudaGetSymbolAddress((void**)&VT, g_VT);
    cudaGetSymbolAddress((void**)&S,  g_S);

    const int nX4 = SEQ * DM / 4, nW4 = DM * DM / 4;
    round_tf32<<<nX4 / 256, 256>>>(Xr, x,  nX4);
    round_tf32<<<nW4 / 256, 256>>>(Wq, wq, nW4);
    round_tf32<<<nW4 / 256, 256>>>(Wk, wk, nW4);
    round_tf32<<<nW4 / 256, 256>>>(Wv, wv, nW4);

    // Q = Xr @ Wq^T   [8192, 2048]  (rna-rounded for the S GEMM)
    gemm_tf32<<<dim3(DM / BN, SEQ / BM), 256, GEMM_SMEM>>>(Q, Xr, Wq, DM, DM, 1.0f, 1);
    // K = Xr @ Wk^T   [8192, 2048]
    gemm_tf32<<<dim3(DM / BN, SEQ / BM), 256, GEMM_SMEM>>>(K, Xr, Wk, DM, DM, 1.0f, 1);
    // VT = Wv @ Xr^T  [2048, 8192]  (V computed pre-transposed, rounded for the O GEMM)
    gemm_tf32<<<dim3(SEQ / BN, DM / BM), 256, GEMM_SMEM>>>(VT, Wv, Xr, SEQ, DM, 1.0f, 1);
    // S = (Q @ K^T) / sqrt(DM)   [8192, 8192]
    gemm_tf32<<<dim3(SEQ / BN, SEQ / BM), 256, GEMM_SMEM>>>(S, Q, K, SEQ, DM,
                                                            0.022097086912079608f, 0);
    // P = softmax(S) in place, rna-rounded
    softmax_rows<<<SEQ, 256>>>(S);
    // out = P @ VT^T   [8192, 2048]
    gemm_tf32<<<dim3(DM / BN, SEQ / BM), 256, GEMM_SMEM>>>(out, S, VT, DM, SEQ, 1.0f, 0);
}

// round 8
// speedup vs baseline: 1.7010x; 1.6639x over previous
#include <cuda_runtime.h>
#include <cuda_fp16.h>
#include <cstdint>
#include <cstddef>

static constexpr int SEQ = 8192;
static constexpr int DM  = 2048;

// ---------------- static device scratch (allocation-free) ----------------
__device__ __align__(256) __half g_Xh[(size_t)SEQ * DM];
__device__ __align__(256) __half g_Wq[(size_t)DM * DM];
__device__ __align__(256) __half g_Wk[(size_t)DM * DM];
__device__ __align__(256) __half g_Wv[(size_t)DM * DM];
__device__ __align__(256) __half g_Q [(size_t)SEQ * DM];
__device__ __align__(256) __half g_K [(size_t)SEQ * DM];
__device__ __align__(256) __half g_VT[(size_t)DM * SEQ];
__device__ __align__(256) float  g_S [(size_t)SEQ * SEQ];   // fp32 scores
__device__ __align__(256) __half g_P [(size_t)SEQ * SEQ];   // fp16 probs

// ---------------- helpers ----------------
__device__ __forceinline__ uint32_t smem_u32(const void* p) {
    uint32_t a;
    asm("{ .reg .u64 t; cvta.to.shared.u64 t, %1; cvt.u32.u64 %0, t; }" : "=r"(a) : "l"(p));
    return a;
}

#define CP_ASYNC16(d, s)  asm volatile("cp.async.cg.shared.global [%0], [%1], 16;" :: "r"((uint32_t)(d)), "l"(s) : "memory")
#define CP_COMMIT()       asm volatile("cp.async.commit_group;" ::: "memory")
#define CP_WAIT1()        asm volatile("cp.async.wait_group 1;" ::: "memory")

// m16n8k16 f16 mma, fp32 accumulate (sm_80+, valid on plain sm_100 target)
__device__ __forceinline__ void mma16(float c[4], const uint32_t a[4], const uint32_t b[2]) {
    asm volatile(
        "mma.sync.aligned.m16n8k16.row.col.f32.f16.f16.f32 "
        "{%0,%1,%2,%3}, {%4,%5,%6,%7}, {%8,%9}, {%0,%1,%2,%3};\n"
        : "+f"(c[0]), "+f"(c[1]), "+f"(c[2]), "+f"(c[3])
        : "r"(a[0]), "r"(a[1]), "r"(a[2]), "r"(a[3]), "r"(b[0]), "r"(b[1]));
}

// ---------------- generic fp16 GEMM: C[m,n] = alpha * sum_k A[m,k]*B[n,k] ----------------
// A:[M,K] half row-major, B:[N,K] half row-major (C = A @ B^T).
// M%256==0, N%128==0, K%32==0. Output fp32 or fp16 (out_half flag).
static constexpr int BM = 256, BN = 128, BK = 32;
static constexpr int PAD = 40;                     // halves per smem row (80B, conflict-free)
static constexpr int A_TILE_H = BM * PAD;          // 10240 halves
static constexpr int B_TILE_H = BN * PAD;          // 5120 halves
static constexpr int STAGE_H  = A_TILE_H + B_TILE_H;
static constexpr int NSTG = 3;
static constexpr size_t GEMM_SMEM = (size_t)NSTG * STAGE_H * 2;   // 92160 B

__device__ __forceinline__ void load_stage(__half* st, const __half* gA, const __half* gB, int K) {
    const int tid = threadIdx.x;
    __half* sA = st;
    __half* sB = st + A_TILE_H;
#pragma unroll
    for (int i = 0; i < 4; i++) {            // A: 256 rows * 4 chunks(16B) = 1024 / 256 thr
        int c = tid + 256 * i;
        int row = c >> 2, ch = c & 3;
        CP_ASYNC16(smem_u32(sA + row * PAD + ch * 8), gA + (size_t)row * K + ch * 8);
    }
#pragma unroll
    for (int i = 0; i < 2; i++) {            // B: 128 rows * 4 chunks = 512
        int c = tid + 256 * i;
        int row = c >> 2, ch = c & 3;
        CP_ASYNC16(smem_u32(sB + row * PAD + ch * 8), gB + (size_t)row * K + ch * 8);
    }
}

__global__ void __launch_bounds__(256, 1)
gemm_f16(void* __restrict__ Cv, const __half* __restrict__ A, const __half* __restrict__ B,
         int N, int K, float alpha, int out_half) {
    extern __shared__ __half smem[];
    const int tid  = threadIdx.x;
    const int wid  = tid >> 5;
    const int lane = tid & 31;
    const int wm = wid & 3;          // 4 warps along M (64 rows each)
    const int wn = wid >> 2;         // 2 warps along N (64 cols each)
    const int g = lane >> 2;         // 0..7
    const int t = lane & 3;          // 0..3

    // tile-order swizzle: chunks of 8 n-tiles, m-major inside a chunk -> compact waves
    const int id = blockIdx.y * gridDim.x + blockIdx.x;
    const int chunk = id / (8 * gridDim.y);
    const int rem   = id % (8 * gridDim.y);
    const int tile_m = (rem / 8) * BM;
    const int tile_n = (chunk * 8 + (rem & 7)) * BN;

    const __half* gA = A + (size_t)tile_m * K;
    const __half* gB = B + (size_t)tile_n * K;

    float acc[4][8][4];
#pragma unroll
    for (int i = 0; i < 4; i++)
#pragma unroll
        for (int j = 0; j < 8; j++)
#pragma unroll
            for (int q = 0; q < 4; q++) acc[i][j][q] = 0.f;

    const int nst = K / BK;

    load_stage(smem,           gA,      gB,      K);  CP_COMMIT();
    load_stage(smem + STAGE_H, gA + BK, gB + BK, K);  CP_COMMIT();

    for (int s = 0; s < nst; s++) {
        CP_WAIT1();
        __syncthreads();

        if (s + 2 < nst)
            load_stage(smem + (size_t)((s + 2) % NSTG) * STAGE_H,
                       gA + (size_t)(s + 2) * BK, gB + (size_t)(s + 2) * BK, K);
        CP_COMMIT();

        const __half* sA = smem + (size_t)(s % NSTG) * STAGE_H;
        const __half* sB = sA + A_TILE_H;

#pragma unroll
        for (int ks = 0; ks < 2; ks++) {     // two k16 steps per BK=32
            const int k0 = ks * 16 + t * 2;
            uint32_t af[4][4];
#pragma unroll
            for (int im = 0; im < 4; im++) {
                const int r = wm * 64 + im * 16 + g;
                af[im][0] = *(const uint32_t*)(sA + r * PAD + k0);
                af[im][1] = *(const uint32_t*)(sA + (r + 8) * PAD + k0);
                af[im][2] = *(const uint32_t*)(sA + r * PAD + k0 + 8);
                af[im][3] = *(const uint32_t*)(sA + (r + 8) * PAD + k0 + 8);
            }
#pragma unroll
            for (int in = 0; in < 8; in++) {
                const int n = wn * 64 + in * 8 + g;
                uint32_t bf[2];
                bf[0] = *(const uint32_t*)(sB + n * PAD + k0);
                bf[1] = *(const uint32_t*)(sB + n * PAD + k0 + 8);
#pragma unroll
                for (int im = 0; im < 4; im++) mma16(acc[im][in], af[im], bf);
            }
        }
    }

    // epilogue
#pragma unroll
    for (int im = 0; im < 4; im++) {
        const int row = tile_m + wm * 64 + im * 16 + g;
#pragma unroll
        for (int in = 0; in < 8; in++) {
            const int col = tile_n + wn * 64 + in * 8 + t * 2;
            float c0 = acc[im][in][0] * alpha, c1 = acc[im][in][1] * alpha;
            float c2 = acc[im][in][2] * alpha, c3 = acc[im][in][3] * alpha;
            if (out_half) {
                __half* C = (__half*)Cv;
                __half2 h0 = __floats2half2_rn(c0, c1);
                __half2 h1 = __floats2half2_rn(c2, c3);
                *(__half2*)(C + (size_t)row * N + col)       = h0;
                *(__half2*)(C + (size_t)(row + 8) * N + col) = h1;
            } else {
                float* C = (float*)Cv;
                *(float2*)(C + (size_t)row * N + col)       = make_float2(c0, c1);
                *(float2*)(C + (size_t)(row + 8) * N + col) = make_float2(c2, c3);
            }
        }
    }
}

// ---------------- row softmax: read fp32 S, write fp16 P ----------------
__global__ void __launch_bounds__(256, 1)
softmax_rows(const float* __restrict__ S, __half* __restrict__ P) {
    const float4* row = (const float4*)(S + (size_t)blockIdx.x * SEQ);
    __half2* prow = (__half2*)(P + (size_t)blockIdx.x * SEQ);
    __shared__ float red[16];
    const int t = threadIdx.x, w = t >> 5;
    float4 v[8];
    float m = -1e30f;
#pragma unroll
    for (int i = 0; i < 8; i++) {
        v[i] = row[t + 256 * i];
        m = fmaxf(m, fmaxf(fmaxf(v[i].x, v[i].y), fmaxf(v[i].z, v[i].w)));
    }
#pragma unroll
    for (int o = 16; o; o >>= 1) m = fmaxf(m, __shfl_xor_sync(~0u, m, o));
    if ((t & 31) == 0) red[w] = m;
    __syncthreads();
    m = red[0];
#pragma unroll
    for (int i = 1; i < 8; i++) m = fmaxf(m, red[i]);

    float s = 0.f;
#pragma unroll
    for (int i = 0; i < 8; i++) {
        v[i].x = __expf(v[i].x - m); v[i].y = __expf(v[i].y - m);
        v[i].z = __expf(v[i].z - m); v[i].w = __expf(v[i].w - m);
        s += (v[i].x + v[i].y) + (v[i].z + v[i].w);
    }
#pragma unroll
    for (int o = 16; o; o >>= 1) s += __shfl_xor_sync(~0u, s, o);
    if ((t & 31) == 0) red[8 + w] = s;
    __syncthreads();
    s = red[8];
#pragma unroll
    for (int i = 9; i < 16; i++) s += red[i];
    const float inv = 1.0f / s;
#pragma unroll
    for (int i = 0; i < 8; i++) {
        prow[2 * (t + 256 * i)]     = __floats2half2_rn(v[i].x * inv, v[i].y * inv);
        prow[2 * (t + 256 * i) + 1] = __floats2half2_rn(v[i].z * inv, v[i].w * inv);
    }
}

// ---------------- fp32 -> fp16 conversion ----------------
__global__ void to_half(__half* __restrict__ dst, const float* __restrict__ src, int n4) {
    int i = blockIdx.x * blockDim.x + threadIdx.x;
    if (i < n4) {
        float4 a = ((const float4*)src)[i];
        __half2 h0 = __floats2half2_rn(a.x, a.y);
        __half2 h1 = __floats2half2_rn(a.z, a.w);
        ((__half2*)dst)[2 * i]     = h0;
        ((__half2*)dst)[2 * i + 1] = h1;
    }
}

// ---------------- launch ----------------
extern "C" void kernel_launch(void* const* d_in, const int* in_sizes, int n_in,
                              void* d_out, int out_size) {
    const float* x  = (const float*)d_in[0];
    const float* wq = (const float*)d_in[1];
    const float* wk = (const float*)d_in[2];
    const float* wv = (const float*)d_in[3];
    float* out = (float*)d_out;

    cudaFuncSetAttribute(gemm_f16, cudaFuncAttributeMaxDynamicSharedMemorySize, (int)GEMM_SMEM);

    __half *Xh, *Wq, *Wk, *Wv, *Q, *K, *VT, *P;
    float *S;
    cudaGetSymbolAddress((void**)&Xh, g_Xh);
    cudaGetSymbolAddress((void**)&Wq, g_Wq);
    cudaGetSymbolAddress((void**)&Wk, g_Wk);
    cudaGetSymbolAddress((void**)&Wv, g_Wv);
    cudaGetSymbolAddress((void**)&Q,  g_Q);
    cudaGetSymbolAddress((void**)&K,  g_K);
    cudaGetSymbolAddress((void**)&VT, g_VT);
    cudaGetSymbolAddress((void**)&S,  g_S);
    cudaGetSymbolAddress((void**)&P,  g_P);

    const int nX4 = SEQ * DM / 4, nW4 = DM * DM / 4;
    to_half<<<nX4 / 256, 256>>>(Xh, x,  nX4);
    to_half<<<nW4 / 256, 256>>>(Wq, wq, nW4);
    to_half<<<nW4 / 256, 256>>>(Wk, wk, nW4);
    to_half<<<nW4 / 256, 256>>>(Wv, wv, nW4);

    // Q = Xh @ Wq^T   [8192, 2048] fp16
    gemm_f16<<<dim3(DM / BN, SEQ / BM), 256, GEMM_SMEM>>>(Q, Xh, Wq, DM, DM, 1.0f, 1);
    // K = Xh @ Wk^T   [8192, 2048] fp16
    gemm_f16<<<dim3(DM / BN, SEQ / BM), 256, GEMM_SMEM>>>(K, Xh, Wk, DM, DM, 1.0f, 1);
    // VT = Wv @ Xh^T  [2048, 8192] fp16  (V computed pre-transposed)
    gemm_f16<<<dim3(SEQ / BN, DM / BM), 256, GEMM_SMEM>>>(VT, Wv, Xh, SEQ, DM, 1.0f, 1);
    // S = (Q @ K^T) / sqrt(DM)   [8192, 8192] fp32
    gemm_f16<<<dim3(SEQ / BN, SEQ / BM), 256, GEMM_SMEM>>>(S, Q, K, SEQ, DM,
                                                           0.022097086912079608f, 0);
    // P = softmax(S), fp16
    softmax_rows<<<SEQ, 256>>>(S, P);
    // out = P @ VT^T   [8192, 2048] fp32
    gemm_f16<<<dim3(DM / BN, SEQ / BM), 256, GEMM_SMEM>>>(out, P, VT, DM, SEQ, 1.0f, 0);
}

// round 9
// speedup vs baseline: 2.0243x; 1.1901x over previous
#include <cuda_runtime.h>
#include <cuda_fp16.h>
#include <cstdint>
#include <cstddef>

static constexpr int SEQ = 8192;
static constexpr int DM  = 2048;

// ---------------- static device scratch (allocation-free) ----------------
__device__ __align__(256) __half g_Xh[(size_t)SEQ * DM];
__device__ __align__(256) __half g_Wq[(size_t)DM * DM];
__device__ __align__(256) __half g_Wk[(size_t)DM * DM];
__device__ __align__(256) __half g_Wv[(size_t)DM * DM];
__device__ __align__(256) __half g_Q [(size_t)SEQ * DM];
__device__ __align__(256) __half g_K [(size_t)SEQ * DM];
__device__ __align__(256) __half g_VT[(size_t)DM * SEQ];
__device__ __align__(256) __half g_Sh[(size_t)SEQ * SEQ];   // fp16 scores -> probs (in place)

// ---------------- helpers ----------------
__device__ __forceinline__ uint32_t smem_u32(const void* p) {
    uint32_t a;
    asm("{ .reg .u64 t; cvta.to.shared.u64 t, %1; cvt.u32.u64 %0, t; }" : "=r"(a) : "l"(p));
    return a;
}

#define CP_ASYNC16(d, s)  asm volatile("cp.async.cg.shared.global [%0], [%1], 16;" :: "r"((uint32_t)(d)), "l"(s) : "memory")
#define CP_COMMIT()       asm volatile("cp.async.commit_group;" ::: "memory")
#define CP_WAIT2()        asm volatile("cp.async.wait_group 2;" ::: "memory")

// m16n8k16 f16 mma, fp32 accumulate (sm_80+, valid on plain sm_100 target)
__device__ __forceinline__ void mma16(float c[4], const uint32_t a[4], const uint32_t b[2]) {
    asm volatile(
        "mma.sync.aligned.m16n8k16.row.col.f32.f16.f16.f32 "
        "{%0,%1,%2,%3}, {%4,%5,%6,%7}, {%8,%9}, {%0,%1,%2,%3};\n"
        : "+f"(c[0]), "+f"(c[1]), "+f"(c[2]), "+f"(c[3])
        : "r"(a[0]), "r"(a[1]), "r"(a[2]), "r"(a[3]), "r"(b[0]), "r"(b[1]));
}

// ---------------- generic fp16 GEMM: C[m,n] = alpha * sum_k A[m,k]*B[n,k] ----------------
// A:[M,K] half row-major, B:[N,K] half row-major (C = A @ B^T).
// M%128==0, N%128==0, K%32==0. Output fp32 or fp16 (out_half flag).
static constexpr int BM = 128, BN = 128, BK = 32;
static constexpr int PAD = 40;                     // halves per smem row (80B, conflict-free)
static constexpr int A_TILE_H = BM * PAD;          // 5120 halves
static constexpr int B_TILE_H = BN * PAD;          // 5120 halves
static constexpr int STAGE_H  = A_TILE_H + B_TILE_H;
static constexpr int NSTG = 4;
static constexpr size_t GEMM_SMEM = (size_t)NSTG * STAGE_H * 2;   // 81920 B -> 2 CTAs/SM

__device__ __forceinline__ void load_stage(__half* st, const __half* gA, const __half* gB, int K) {
    const int tid = threadIdx.x;      // 128 threads
    __half* sA = st;
    __half* sB = st + A_TILE_H;
#pragma unroll
    for (int i = 0; i < 4; i++) {     // A: 128 rows * 4 chunks(16B) = 512 / 128 thr
        int c = tid + 128 * i;
        int row = c >> 2, ch = c & 3;
        CP_ASYNC16(smem_u32(sA + row * PAD + ch * 8), gA + (size_t)row * K + ch * 8);
    }
#pragma unroll
    for (int i = 0; i < 4; i++) {     // B: same shape
        int c = tid + 128 * i;
        int row = c >> 2, ch = c & 3;
        CP_ASYNC16(smem_u32(sB + row * PAD + ch * 8), gB + (size_t)row * K + ch * 8);
    }
}

__global__ void __launch_bounds__(128, 2)
gemm_f16(void* __restrict__ Cv, const __half* __restrict__ A, const __half* __restrict__ B,
         int N, int K, float alpha, int out_half) {
    extern __shared__ __half smem[];
    const int tid  = threadIdx.x;
    const int wid  = tid >> 5;
    const int lane = tid & 31;
    const int wm = wid & 1;          // 2 warps along M (64 rows each)
    const int wn = wid >> 1;         // 2 warps along N (64 cols each)
    const int g = lane >> 2;         // 0..7
    const int t = lane & 3;          // 0..3

    // tile-order swizzle: chunks of 8 n-tiles, m-major inside a chunk -> compact waves
    const int id = blockIdx.y * gridDim.x + blockIdx.x;
    const int chunk = id / (8 * gridDim.y);
    const int rem   = id % (8 * gridDim.y);
    const int tile_m = (rem / 8) * BM;
    const int tile_n = (chunk * 8 + (rem & 7)) * BN;

    const __half* gA = A + (size_t)tile_m * K;
    const __half* gB = B + (size_t)tile_n * K;

    float acc[4][8][4];
#pragma unroll
    for (int i = 0; i < 4; i++)
#pragma unroll
        for (int j = 0; j < 8; j++)
#pragma unroll
            for (int q = 0; q < 4; q++) acc[i][j][q] = 0.f;

    const int nst = K / BK;

    load_stage(smem,               gA,          gB,          K);  CP_COMMIT();
    load_stage(smem + STAGE_H,     gA + BK,     gB + BK,     K);  CP_COMMIT();
    load_stage(smem + 2 * STAGE_H, gA + 2 * BK, gB + 2 * BK, K);  CP_COMMIT();

    for (int s = 0; s < nst; s++) {
        CP_WAIT2();              // stage s resident (<=2 newer groups pending)
        __syncthreads();

        if (s + 3 < nst)
            load_stage(smem + (size_t)((s + 3) % NSTG) * STAGE_H,
                       gA + (size_t)(s + 3) * BK, gB + (size_t)(s + 3) * BK, K);
        CP_COMMIT();

        const __half* sA = smem + (size_t)(s % NSTG) * STAGE_H;
        const __half* sB = sA + A_TILE_H;

#pragma unroll
        for (int ks = 0; ks < 2; ks++) {     // two k16 steps per BK=32
            const int k0 = ks * 16 + t * 2;
            uint32_t af[4][4];
#pragma unroll
            for (int im = 0; im < 4; im++) {
                const int r = wm * 64 + im * 16 + g;
                af[im][0] = *(const uint32_t*)(sA + r * PAD + k0);
                af[im][1] = *(const uint32_t*)(sA + (r + 8) * PAD + k0);
                af[im][2] = *(const uint32_t*)(sA + r * PAD + k0 + 8);
                af[im][3] = *(const uint32_t*)(sA + (r + 8) * PAD + k0 + 8);
            }
#pragma unroll
            for (int in = 0; in < 8; in++) {
                const int n = wn * 64 + in * 8 + g;
                uint32_t bf[2];
                bf[0] = *(const uint32_t*)(sB + n * PAD + k0);
                bf[1] = *(const uint32_t*)(sB + n * PAD + k0 + 8);
#pragma unroll
                for (int im = 0; im < 4; im++) mma16(acc[im][in], af[im], bf);
            }
        }
    }

    // epilogue
#pragma unroll
    for (int im = 0; im < 4; im++) {
        const int row = tile_m + wm * 64 + im * 16 + g;
#pragma unroll
        for (int in = 0; in < 8; in++) {
            const int col = tile_n + wn * 64 + in * 8 + t * 2;
            float c0 = acc[im][in][0] * alpha, c1 = acc[im][in][1] * alpha;
            float c2 = acc[im][in][2] * alpha, c3 = acc[im][in][3] * alpha;
            if (out_half) {
                __half* C = (__half*)Cv;
                *(__half2*)(C + (size_t)row * N + col)       = __floats2half2_rn(c0, c1);
                *(__half2*)(C + (size_t)(row + 8) * N + col) = __floats2half2_rn(c2, c3);
            } else {
                float* C = (float*)Cv;
                *(float2*)(C + (size_t)row * N + col)       = make_float2(c0, c1);
                *(float2*)(C + (size_t)(row + 8) * N + col) = make_float2(c2, c3);
            }
        }
    }
}

// ---------------- row softmax, in place on fp16 S ----------------
__global__ void __launch_bounds__(256, 1)
softmax_rows(__half* __restrict__ S) {
    uint4* row = (uint4*)(S + (size_t)blockIdx.x * SEQ);   // 8 halves per uint4
    __shared__ float red[16];
    const int t = threadIdx.x, w = t >> 5;

    float v[32];
    float m = -1e30f;
#pragma unroll
    for (int i = 0; i < 4; i++) {                 // 1024 uint4 per row / 256 thr = 4
        uint4 u = row[t + 256 * i];
        const __half2* h = (const __half2*)&u;
#pragma unroll
        for (int j = 0; j < 4; j++) {
            float2 f = __half22float2(h[j]);
            v[i * 8 + 2 * j]     = f.x;
            v[i * 8 + 2 * j + 1] = f.y;
            m = fmaxf(m, fmaxf(f.x, f.y));
        }
    }
#pragma unroll
    for (int o = 16; o; o >>= 1) m = fmaxf(m, __shfl_xor_sync(~0u, m, o));
    if ((t & 31) == 0) red[w] = m;
    __syncthreads();
    m = red[0];
#pragma unroll
    for (int i = 1; i < 8; i++) m = fmaxf(m, red[i]);

    float s = 0.f;
#pragma unroll
    for (int i = 0; i < 32; i++) { v[i] = __expf(v[i] - m); s += v[i]; }
#pragma unroll
    for (int o = 16; o; o >>= 1) s += __shfl_xor_sync(~0u, s, o);
    if ((t & 31) == 0) red[8 + w] = s;
    __syncthreads();
    s = red[8];
#pragma unroll
    for (int i = 9; i < 16; i++) s += red[i];
    const float inv = 1.0f / s;

#pragma unroll
    for (int i = 0; i < 4; i++) {
        uint4 u;
        __half2* h = (__half2*)&u;
#pragma unroll
        for (int j = 0; j < 4; j++)
            h[j] = __floats2half2_rn(v[i * 8 + 2 * j] * inv, v[i * 8 + 2 * j + 1] * inv);
        row[t + 256 * i] = u;
    }
}

// ---------------- fp32 -> fp16 conversion ----------------
__global__ void to_half(__half* __restrict__ dst, const float* __restrict__ src, int n4) {
    int i = blockIdx.x * blockDim.x + threadIdx.x;
    if (i < n4) {
        float4 a = ((const float4*)src)[i];
        ((__half2*)dst)[2 * i]     = __floats2half2_rn(a.x, a.y);
        ((__half2*)dst)[2 * i + 1] = __floats2half2_rn(a.z, a.w);
    }
}

// ---------------- launch ----------------
extern "C" void kernel_launch(void* const* d_in, const int* in_sizes, int n_in,
                              void* d_out, int out_size) {
    const float* x  = (const float*)d_in[0];
    const float* wq = (const float*)d_in[1];
    const float* wk = (const float*)d_in[2];
    const float* wv = (const float*)d_in[3];
    float* out = (float*)d_out;

    cudaFuncSetAttribute(gemm_f16, cudaFuncAttributeMaxDynamicSharedMemorySize, (int)GEMM_SMEM);

    __half *Xh, *Wq, *Wk, *Wv, *Q, *K, *VT, *Sh;
    cudaGetSymbolAddress((void**)&Xh, g_Xh);
    cudaGetSymbolAddress((void**)&Wq, g_Wq);
    cudaGetSymbolAddress((void**)&Wk, g_Wk);
    cudaGetSymbolAddress((void**)&Wv, g_Wv);
    cudaGetSymbolAddress((void**)&Q,  g_Q);
    cudaGetSymbolAddress((void**)&K,  g_K);
    cudaGetSymbolAddress((void**)&VT, g_VT);
    cudaGetSymbolAddress((void**)&Sh, g_Sh);

    const int nX4 = SEQ * DM / 4, nW4 = DM * DM / 4;
    to_half<<<nX4 / 256, 256>>>(Xh, x,  nX4);
    to_half<<<nW4 / 256, 256>>>(Wq, wq, nW4);
    to_half<<<nW4 / 256, 256>>>(Wk, wk, nW4);
    to_half<<<nW4 / 256, 256>>>(Wv, wv, nW4);

    // Q = Xh @ Wq^T   [8192, 2048] fp16
    gemm_f16<<<dim3(DM / BN, SEQ / BM), 128, GEMM_SMEM>>>(Q, Xh, Wq, DM, DM, 1.0f, 1);
    // K = Xh @ Wk^T   [8192, 2048] fp16
    gemm_f16<<<dim3(DM / BN, SEQ / BM), 128, GEMM_SMEM>>>(K, Xh, Wk, DM, DM, 1.0f, 1);
    // VT = Wv @ Xh^T  [2048, 8192] fp16  (V computed pre-transposed)
    gemm_f16<<<dim3(SEQ / BN, DM / BM), 128, GEMM_SMEM>>>(VT, Wv, Xh, SEQ, DM, 1.0f, 1);
    // S = (Q @ K^T) / sqrt(DM)   [8192, 8192] fp16
    gemm_f16<<<dim3(SEQ / BN, SEQ / BM), 128, GEMM_SMEM>>>(Sh, Q, K, SEQ, DM,
                                                           0.022097086912079608f, 1);
    // P = softmax(S) in place (fp16)
    softmax_rows<<<SEQ, 256>>>(Sh);
    // out = P @ VT^T   [8192, 2048] fp32
    gemm_f16<<<dim3(DM / BN, SEQ / BM), 128, GEMM_SMEM>>>(out, Sh, VT, DM, SEQ, 1.0f, 0);
}